// round 9
// baseline (speedup 1.0000x reference)
#include <cuda_runtime.h>
#include <cuda_bf16.h>
#include <cstdint>

// ---------------- problem constants ----------------
#define Nn 4096
#define Mm 4096
#define Dd 1024

// ---------------- GEMM tiling ----------------
#define BM 128
#define BN 128
#define BK 64
#define SKEW 8
#define BKP (BK + SKEW)            // 72 bf16 = 144B rows; ldmatrix conflict-free
#define KT (Dd / BK)               // 16 iterations per CTA
#define NSPLIT 32
#define STAGES 3
#define THREADS 128                // 4 warps: 2m x 2n grid of 64x64 warp tiles

#define A_SZ (BM * BKP * 2)        // 18432 B
#define B_SZ (BN * BKP * 2)        // 18432 B
#define STG (A_SZ + B_SZ)          // 36864 B
#define DYN_SMEM (STAGES * STG)    // 110592 B (x2 CTA/SM = 221 KB)

#define GRID_TILES (Mm / BM * NSPLIT)   // 1024 CTAs

// ---------------- scratch ----------------
__device__ __align__(256) __nv_bfloat16 g_zb[Nn * Dd];
__device__ __align__(256) __nv_bfloat16 g_eb[Mm * Dd];
__device__ __align__(256) float g_zsq[Nn];
__device__ __align__(256) float g_esq[Mm];
__device__ __align__(256) unsigned g_rowmin[Mm];   // full-distance bits (positive float)
__device__ unsigned g_done;

// ---------------- PTX helpers ----------------
__device__ __forceinline__ void cp_async16(uint32_t saddr, const void* gptr) {
    asm volatile("cp.async.cg.shared.global [%0], [%1], 16;\n" ::"r"(saddr), "l"(gptr));
}
__device__ __forceinline__ void cp_commit() { asm volatile("cp.async.commit_group;\n"); }
template <int NW>
__device__ __forceinline__ void cp_wait() { asm volatile("cp.async.wait_group %0;\n" ::"n"(NW)); }

__device__ __forceinline__ void ldsm4(uint32_t* r, uint32_t saddr) {
    asm volatile("ldmatrix.sync.aligned.m8n8.x4.shared.b16 {%0,%1,%2,%3}, [%4];\n"
                 : "=r"(r[0]), "=r"(r[1]), "=r"(r[2]), "=r"(r[3])
                 : "r"(saddr));
}
__device__ __forceinline__ void mma16816(float* c, const uint32_t* a, uint32_t b0, uint32_t b1) {
    asm volatile(
        "mma.sync.aligned.m16n8k16.row.col.f32.bf16.bf16.f32 "
        "{%0,%1,%2,%3}, {%4,%5,%6,%7}, {%8,%9}, {%0,%1,%2,%3};\n"
        : "+f"(c[0]), "+f"(c[1]), "+f"(c[2]), "+f"(c[3])
        : "r"(a[0]), "r"(a[1]), "r"(a[2]), "r"(a[3]), "r"(b0), "r"(b1));
}

// ================= kernel 1: convert + squared norms + result-buffer init ==========
__global__ void __launch_bounds__(256) convert_kernel(const float* __restrict__ z,
                                                      const float* __restrict__ e) {
    if (blockIdx.x == 0) {
#pragma unroll
        for (int i = 0; i < Mm / 256; i++) g_rowmin[threadIdx.x + 256 * i] = 0x7f800000u;
        if (threadIdx.x == 0) g_done = 0u;
    }
    const int gwarp = (blockIdx.x * 256 + threadIdx.x) >> 5;
    const int lane = threadIdx.x & 31;
    const float* src;
    __nv_bfloat16* dst;
    float* sqo;
    if (gwarp < Nn) {
        src = z + (size_t)gwarp * Dd;
        dst = g_zb + (size_t)gwarp * Dd;
        sqo = g_zsq + gwarp;
    } else {
        const int r = gwarp - Nn;
        src = e + (size_t)r * Dd;
        dst = g_eb + (size_t)r * Dd;
        sqo = g_esq + r;
    }
    float s = 0.f;
    const float4* s4 = reinterpret_cast<const float4*>(src);
    uint4* d4 = reinterpret_cast<uint4*>(dst);
#pragma unroll
    for (int i = 0; i < 4; i++) {
        const int idx = lane + 32 * i;
        float4 v0 = s4[2 * idx];
        float4 v1 = s4[2 * idx + 1];
        __nv_bfloat162 p0 = __floats2bfloat162_rn(v0.x, v0.y);
        __nv_bfloat162 p1 = __floats2bfloat162_rn(v0.z, v0.w);
        __nv_bfloat162 p2 = __floats2bfloat162_rn(v1.x, v1.y);
        __nv_bfloat162 p3 = __floats2bfloat162_rn(v1.z, v1.w);
        uint4 w;
        w.x = *reinterpret_cast<unsigned*>(&p0);
        w.y = *reinterpret_cast<unsigned*>(&p1);
        w.z = *reinterpret_cast<unsigned*>(&p2);
        w.w = *reinterpret_cast<unsigned*>(&p3);
        d4[idx] = w;
        s += v0.x * v0.x + v0.y * v0.y + v0.z * v0.z + v0.w * v0.w;
        s += v1.x * v1.x + v1.y * v1.y + v1.z * v1.z + v1.w * v1.w;
    }
#pragma unroll
    for (int o = 16; o; o >>= 1) s += __shfl_xor_sync(0xffffffffu, s, o);
    if (lane == 0) *sqo = s;
}

// ================= kernel 2: GEMM + row-min + fused final reduction =================
// CTA: 128x128 tile, K=1024. 4 warps (2m x 2n), warp tile 64x64 (acc=128 regs),
// explicit fragment double-buffering, 3-stage cp.async, 2 CTA/SM.
__global__ void __launch_bounds__(THREADS, 2) gemm_min_kernel(float* __restrict__ out) {
    extern __shared__ char dyn_raw[];
    __shared__ float srm[2][BM];
    __shared__ float ws[4];

    const uint32_t smem = (uint32_t)__cvta_generic_to_shared(dyn_raw);

    const int tid = threadIdx.x;
    const int lane = tid & 31;
    const int warp = tid >> 5;
    const int wm = warp >> 1;        // 0..1 : 64-row group
    const int wn = warp & 1;         // 0..1 : 64-col group

    const int m0 = blockIdx.x * BM;
    const int n0 = blockIdx.y * BN;

    // cp.async: one full 128B row per thread for A and for B (8 chunks each)
    const int lrow = tid;            // 0..127

    // ldmatrix lane mapping
    const int ldrow = lane & 15;
    const int ldcol = (lane >> 4) * 8;

    float acc[4][8][4];              // 128 regs
#pragma unroll
    for (int mi = 0; mi < 4; mi++)
#pragma unroll
        for (int g = 0; g < 8; g++)
#pragma unroll
            for (int q = 0; q < 4; q++) acc[mi][g][q] = 0.f;

    auto issue = [&](int j, int slot) {
        const int k0 = j * BK;
        const uint32_t sa = smem + slot * STG;
        const uint32_t sb = sa + A_SZ;
        const __nv_bfloat16* gA = g_eb + (size_t)(m0 + lrow) * Dd + k0;
        const __nv_bfloat16* gB = g_zb + (size_t)(n0 + lrow) * Dd + k0;
        const uint32_t dA = sa + (uint32_t)(lrow * BKP) * 2;
        const uint32_t dB = sb + (uint32_t)(lrow * BKP) * 2;
#pragma unroll
        for (int c = 0; c < 8; c++) {
            cp_async16(dA + c * 16, gA + c * 8);
            cp_async16(dB + c * 16, gB + c * 8);
        }
    };

    issue(0, 0);
    cp_commit();
    issue(1, 1);
    cp_commit();

    uint32_t fa[2][4][4];   // [buf][mi][frag] : 32 regs
    uint32_t fb[2][4][4];   // [buf][g][frag]  : 32 regs

    int cslot = 0, islot = 2;
    for (int j = 0; j < KT; j++) {
        cp_wait<1>();
        __syncthreads();

        if (j + 2 < KT) issue(j + 2, islot);
        cp_commit();
        if (++islot == STAGES) islot = 0;

        const uint32_t sa = smem + cslot * STG;
        const uint32_t sb = sa + A_SZ;
        if (++cslot == STAGES) cslot = 0;

        auto load_frags = [&](int ks, int buf) {
#pragma unroll
            for (int mi = 0; mi < 4; mi++)
                ldsm4(fa[buf][mi],
                      sa + (uint32_t)((wm * 64 + mi * 16 + ldrow) * BKP + ks * 16 + ldcol) * 2);
#pragma unroll
            for (int g = 0; g < 4; g++)
                ldsm4(fb[buf][g],
                      sb + (uint32_t)((wn * 64 + g * 16 + ldrow) * BKP + ks * 16 + ldcol) * 2);
        };

        load_frags(0, 0);
#pragma unroll
        for (int ks = 0; ks < 4; ks++) {
            const int cur = ks & 1;
            if (ks < 3) load_frags(ks + 1, cur ^ 1);   // prefetch next step's fragments
#pragma unroll
            for (int g = 0; g < 4; g++) {
#pragma unroll
                for (int mi = 0; mi < 4; mi++) {
                    mma16816(acc[mi][2 * g], fa[cur][mi], fb[cur][g][0], fb[cur][g][2]);
                    mma16816(acc[mi][2 * g + 1], fa[cur][mi], fb[cur][g][1], fb[cur][g][3]);
                }
            }
        }
    }

    // ---- epilogue: v = zsq[n] - 2*acc ; per-row min ----
    const float INF = __int_as_float(0x7f800000);
    float rm[4][2];
#pragma unroll
    for (int mi = 0; mi < 4; mi++) { rm[mi][0] = INF; rm[mi][1] = INF; }

    const int colbase = n0 + wn * 64 + (lane & 3) * 2;
#pragma unroll
    for (int g = 0; g < 8; g++) {
        const int col = colbase + g * 8;
        const float zs0 = g_zsq[col];
        const float zs1 = g_zsq[col + 1];
#pragma unroll
        for (int mi = 0; mi < 4; mi++) {
            const float v0 =
                fminf(fmaf(-2.f, acc[mi][g][0], zs0), fmaf(-2.f, acc[mi][g][1], zs1));
            const float v1 =
                fminf(fmaf(-2.f, acc[mi][g][2], zs0), fmaf(-2.f, acc[mi][g][3], zs1));
            rm[mi][0] = fminf(rm[mi][0], v0);
            rm[mi][1] = fminf(rm[mi][1], v1);
        }
    }

#pragma unroll
    for (int off = 1; off <= 2; off <<= 1) {
#pragma unroll
        for (int mi = 0; mi < 4; mi++) {
            rm[mi][0] = fminf(rm[mi][0], __shfl_xor_sync(0xffffffffu, rm[mi][0], off));
            rm[mi][1] = fminf(rm[mi][1], __shfl_xor_sync(0xffffffffu, rm[mi][1], off));
        }
    }
    if ((lane & 3) == 0) {
        const int r = lane >> 2;
#pragma unroll
        for (int mi = 0; mi < 4; mi++) {
            srm[wn][wm * 64 + mi * 16 + r] = rm[mi][0];
            srm[wn][wm * 64 + mi * 16 + r + 8] = rm[mi][1];
        }
    }
    __syncthreads();
    if (tid < BM) {
        const float v = fminf(srm[0][tid], srm[1][tid]) + g_esq[m0 + tid];
        atomicMin(&g_rowmin[m0 + tid], __float_as_uint(v));
    }

    // ---- last-CTA fused final reduction ----
    __shared__ unsigned s_last;
    __threadfence();
    __syncthreads();
    if (tid == 0) s_last = atomicAdd(&g_done, 1u);
    __syncthreads();
    if (s_last == GRID_TILES - 1) {
        __threadfence();
        float s = 0.f;
#pragma unroll
        for (int i = 0; i < Mm / THREADS; i++)
            s += __uint_as_float(g_rowmin[tid + THREADS * i]);
#pragma unroll
        for (int o = 16; o; o >>= 1) s += __shfl_xor_sync(0xffffffffu, s, o);
        if ((tid & 31) == 0) ws[tid >> 5] = s;
        __syncthreads();
        if (tid == 0) {
            float tot = 0.f;
#pragma unroll
            for (int i = 0; i < 4; i++) tot += ws[i];
            out[0] = tot / (float)Mm;
        }
    }
}

// ================= entry point =================
extern "C" void kernel_launch(void* const* d_in, const int* in_sizes, int n_in,
                              void* d_out, int out_size) {
    const float* z = (const float*)d_in[0];  // [4096, 1024]
    const float* e = (const float*)d_in[1];  // [4096, 1024]
    float* out = (float*)d_out;              // [1]

    convert_kernel<<<(Nn + Mm) / 8, 256>>>(z, e);

    static bool attr_set = false;
    if (!attr_set) {
        cudaFuncSetAttribute(gemm_min_kernel, cudaFuncAttributeMaxDynamicSharedMemorySize,
                             DYN_SMEM);
        attr_set = true;
    }
    dim3 grid(Mm / BM, NSPLIT);  // 32 x 32 = 1024 CTAs
    gemm_min_kernel<<<grid, THREADS, DYN_SMEM>>>(out);
}

// round 10
// speedup vs baseline: 1.9185x; 1.9185x over previous
#include <cuda_runtime.h>
#include <cuda.h>
#include <cuda_bf16.h>
#include <cstdint>

// ---------------- problem constants ----------------
#define Nn 4096
#define Mm 4096
#define Dd 1024

// ---------------- GEMM tiling ----------------
#define BM 128
#define BN 128
#define BK 64                      // 64 bf16 = 128B rows (SW128 atom width)
#define KT (Dd / BK)               // 16 iterations
#define NSPLIT 32
#define STAGES 3
#define NCW 16                     // consumer warps (4m x 4n of 32x32 tiles)
#define THREADS (NCW * 32 + 32)    // +1 producer warp = 544

#define A_SZ (BM * 128)            // 16384 B (swizzled 128B rows)
#define B_SZ (BN * 128)            // 16384 B
#define STG (A_SZ + B_SZ)          // 32768 B
#define DYN_SMEM (STAGES * STG + 1024)

#define GRID_TILES (Mm / BM * NSPLIT)   // 1024 CTAs

// ---------------- scratch ----------------
__device__ __align__(256) __nv_bfloat16 g_zb[Nn * Dd];
__device__ __align__(256) __nv_bfloat16 g_eb[Mm * Dd];
__device__ __align__(256) float g_zsq[Nn];
__device__ __align__(256) float g_esq[Mm];
__device__ __align__(256) unsigned g_rowmin[Mm];   // full-distance bits (positive float)
__device__ unsigned g_done;

// ---------------- PTX helpers ----------------
#define MBARRIER_INIT(addr, cnt) \
    asm volatile("mbarrier.init.shared.b64 [%0], %1;" ::"r"(addr), "r"(cnt) : "memory")
#define MBARRIER_EXPECT_TX(addr, bytes) \
    asm volatile("mbarrier.arrive.expect_tx.shared.b64 _, [%0], %1;" ::"r"(addr), "r"(bytes) : "memory")
#define MBARRIER_ARRIVE(addr) \
    asm volatile("mbarrier.arrive.shared.b64 _, [%0];" ::"r"(addr) : "memory")

__device__ __forceinline__ void mbar_wait(uint32_t addr, uint32_t parity) {
    asm volatile(
        "{\n\t.reg .pred P;\n\t"
        "WL%=:\n\t"
        "mbarrier.try_wait.parity.acquire.cta.shared::cta.b64 P, [%0], %1, 0x989680;\n\t"
        "@P bra.uni WD%=;\n\t"
        "bra.uni WL%=;\n\t"
        "WD%=:\n\t}"
        ::"r"(addr), "r"(parity) : "memory");
}
__device__ __forceinline__ void mbar_wait_relaxed(uint32_t addr, uint32_t parity) {
    asm volatile(
        "{\n\t.reg .pred P;\n\t"
        "WL%=:\n\t"
        "mbarrier.try_wait.parity.relaxed.cta.shared::cta.b64 P, [%0], %1, 0x989680;\n\t"
        "@P bra.uni WD%=;\n\t"
        "bra.uni WL%=;\n\t"
        "WD%=:\n\t}"
        ::"r"(addr), "r"(parity) : "memory");
}

__device__ __forceinline__ void tma_load_2d(uint32_t smem_addr, const void* map,
                                            int cx, int cy, uint32_t mbar) {
    asm volatile(
        "cp.async.bulk.tensor.2d.shared::cta.global.tile.mbarrier::complete_tx::bytes "
        "[%0], [%1, {%2, %3}], [%4];"
        ::"r"(smem_addr), "l"(map), "r"(cx), "r"(cy), "r"(mbar)
        : "memory");
}

__device__ __forceinline__ void ldsm4(uint32_t* r, uint32_t saddr) {
    asm volatile("ldmatrix.sync.aligned.m8n8.x4.shared.b16 {%0,%1,%2,%3}, [%4];\n"
                 : "=r"(r[0]), "=r"(r[1]), "=r"(r[2]), "=r"(r[3])
                 : "r"(saddr));
}
__device__ __forceinline__ void mma16816(float* c, const uint32_t* a, uint32_t b0, uint32_t b1) {
    asm volatile(
        "mma.sync.aligned.m16n8k16.row.col.f32.bf16.bf16.f32 "
        "{%0,%1,%2,%3}, {%4,%5,%6,%7}, {%8,%9}, {%0,%1,%2,%3};\n"
        : "+f"(c[0]), "+f"(c[1]), "+f"(c[2]), "+f"(c[3])
        : "r"(a[0]), "r"(a[1]), "r"(a[2]), "r"(a[3]), "r"(b0), "r"(b1));
}

// swizzled smem address of 16B chunk (row, cc) in a 128B-row SW128 tile
__device__ __forceinline__ uint32_t swz(uint32_t base, int row, int cc) {
    return base + ((uint32_t)row << 7) + (((uint32_t)(cc ^ (row & 7))) << 4);
}

// ================= kernel 1: convert + squared norms + result-buffer init ==========
__global__ void __launch_bounds__(256) convert_kernel(const float* __restrict__ z,
                                                      const float* __restrict__ e) {
    if (blockIdx.x == 0) {
#pragma unroll
        for (int i = 0; i < Mm / 256; i++) g_rowmin[threadIdx.x + 256 * i] = 0x7f800000u;
        if (threadIdx.x == 0) g_done = 0u;
    }
    const int gwarp = (blockIdx.x * 256 + threadIdx.x) >> 5;
    const int lane = threadIdx.x & 31;
    const float* src;
    __nv_bfloat16* dst;
    float* sqo;
    if (gwarp < Nn) {
        src = z + (size_t)gwarp * Dd;
        dst = g_zb + (size_t)gwarp * Dd;
        sqo = g_zsq + gwarp;
    } else {
        const int r = gwarp - Nn;
        src = e + (size_t)r * Dd;
        dst = g_eb + (size_t)r * Dd;
        sqo = g_esq + r;
    }
    float s = 0.f;
    const float4* s4 = reinterpret_cast<const float4*>(src);
    uint4* d4 = reinterpret_cast<uint4*>(dst);
#pragma unroll
    for (int i = 0; i < 4; i++) {
        const int idx = lane + 32 * i;
        float4 v0 = s4[2 * idx];
        float4 v1 = s4[2 * idx + 1];
        __nv_bfloat162 p0 = __floats2bfloat162_rn(v0.x, v0.y);
        __nv_bfloat162 p1 = __floats2bfloat162_rn(v0.z, v0.w);
        __nv_bfloat162 p2 = __floats2bfloat162_rn(v1.x, v1.y);
        __nv_bfloat162 p3 = __floats2bfloat162_rn(v1.z, v1.w);
        uint4 w;
        w.x = *reinterpret_cast<unsigned*>(&p0);
        w.y = *reinterpret_cast<unsigned*>(&p1);
        w.z = *reinterpret_cast<unsigned*>(&p2);
        w.w = *reinterpret_cast<unsigned*>(&p3);
        d4[idx] = w;
        s += v0.x * v0.x + v0.y * v0.y + v0.z * v0.z + v0.w * v0.w;
        s += v1.x * v1.x + v1.y * v1.y + v1.z * v1.z + v1.w * v1.w;
    }
#pragma unroll
    for (int o = 16; o; o >>= 1) s += __shfl_xor_sync(0xffffffffu, s, o);
    if (lane == 0) *sqo = s;
}

// ================= kernel 2: TMA-fed GEMM + row-min + fused reduction =================
// 544 threads: warps 0-15 consume (4m x 4n of 32x32 tiles), warp 16 lane 0 produces
// via TMA into a 3-stage mbarrier ring. No __syncthreads in mainloop.
__global__ void __launch_bounds__(THREADS, 2) gemm_min_kernel(
    float* __restrict__ out,
    const __grid_constant__ CUtensorMap tmA,
    const __grid_constant__ CUtensorMap tmB) {
    extern __shared__ char dyn_raw[];
    __shared__ __align__(8) uint64_t s_bar[2 * STAGES];   // full[0..2], empty[0..2]
    __shared__ float srm[4][BM];
    __shared__ float ws[17];
    __shared__ unsigned s_last;

    uint32_t dynb = (uint32_t)__cvta_generic_to_shared(dyn_raw);
    dynb = (dynb + 1023u) & ~1023u;
    const uint32_t barb = (uint32_t)__cvta_generic_to_shared(s_bar);
#define BAR_FULL(s) (barb + (uint32_t)(s) * 8u)
#define BAR_EMPTY(s) (barb + (uint32_t)(STAGES + (s)) * 8u)

    const int tid = threadIdx.x;
    const int lane = tid & 31;
    const int warp = tid >> 5;

    const int m0 = blockIdx.x * BM;
    const int n0 = blockIdx.y * BN;

    if (tid == 0) {
#pragma unroll
        for (int s = 0; s < STAGES; s++) {
            MBARRIER_INIT(BAR_FULL(s), 1);
            MBARRIER_INIT(BAR_EMPTY(s), NCW);
        }
    }
    __syncthreads();

    if (warp < NCW) {
        // ---------------- consumers ----------------
        const int wm = warp >> 2;        // 0..3 : 32-row group
        const int wn = warp & 3;         // 0..3 : 32-col group
        const int ldrow = lane & 15;
        const int ldcc = lane >> 4;      // 16B-chunk parity within the 32B k-step

        float acc[2][4][4];
#pragma unroll
        for (int mi = 0; mi < 2; mi++)
#pragma unroll
            for (int g = 0; g < 4; g++)
#pragma unroll
                for (int q = 0; q < 4; q++) acc[mi][g][q] = 0.f;

        int slot = 0, ph = 0;
        for (int j = 0; j < KT; j++) {
            mbar_wait(BAR_FULL(slot), (uint32_t)ph);
            const uint32_t sa = dynb + slot * STG;
            const uint32_t sb = sa + A_SZ;

#pragma unroll
            for (int ks = 0; ks < 4; ks++) {
                const int cc = ks * 2 + ldcc;
                uint32_t a[2][4];
#pragma unroll
                for (int mi = 0; mi < 2; mi++)
                    ldsm4(a[mi], swz(sa, wm * 32 + mi * 16 + ldrow, cc));
                uint32_t b[2][4];
#pragma unroll
                for (int h = 0; h < 2; h++)
                    ldsm4(b[h], swz(sb, wn * 32 + h * 16 + ldrow, cc));
#pragma unroll
                for (int h = 0; h < 2; h++) {
#pragma unroll
                    for (int mi = 0; mi < 2; mi++) {
                        mma16816(acc[mi][2 * h], a[mi], b[h][0], b[h][2]);
                        mma16816(acc[mi][2 * h + 1], a[mi], b[h][1], b[h][3]);
                    }
                }
            }
            __syncwarp();
            if (lane == 0) MBARRIER_ARRIVE(BAR_EMPTY(slot));
            if (++slot == STAGES) { slot = 0; ph ^= 1; }
        }

        // ---- epilogue: v = zsq[n] - 2*acc ; per-row min ----
        const float INF = __int_as_float(0x7f800000);
        float rm0 = INF, rm1 = INF, rm2 = INF, rm3 = INF;
        const int colbase = n0 + wn * 32 + (lane & 3) * 2;
#pragma unroll
        for (int g = 0; g < 4; g++) {
            const int col = colbase + g * 8;
            const float zs0 = g_zsq[col];
            const float zs1 = g_zsq[col + 1];
            {
                const float v0 = fminf(fmaf(-2.f, acc[0][g][0], zs0), fmaf(-2.f, acc[0][g][1], zs1));
                const float v1 = fminf(fmaf(-2.f, acc[0][g][2], zs0), fmaf(-2.f, acc[0][g][3], zs1));
                rm0 = fminf(rm0, v0);
                rm1 = fminf(rm1, v1);
            }
            {
                const float v0 = fminf(fmaf(-2.f, acc[1][g][0], zs0), fmaf(-2.f, acc[1][g][1], zs1));
                const float v1 = fminf(fmaf(-2.f, acc[1][g][2], zs0), fmaf(-2.f, acc[1][g][3], zs1));
                rm2 = fminf(rm2, v0);
                rm3 = fminf(rm3, v1);
            }
        }
#pragma unroll
        for (int off = 1; off <= 2; off <<= 1) {
            rm0 = fminf(rm0, __shfl_xor_sync(0xffffffffu, rm0, off));
            rm1 = fminf(rm1, __shfl_xor_sync(0xffffffffu, rm1, off));
            rm2 = fminf(rm2, __shfl_xor_sync(0xffffffffu, rm2, off));
            rm3 = fminf(rm3, __shfl_xor_sync(0xffffffffu, rm3, off));
        }
        if ((lane & 3) == 0) {
            const int r = lane >> 2;
            srm[wn][wm * 32 + r] = rm0;
            srm[wn][wm * 32 + r + 8] = rm1;
            srm[wn][wm * 32 + 16 + r] = rm2;
            srm[wn][wm * 32 + 24 + r] = rm3;
        }
    } else if (lane == 0) {
        // ---------------- producer (warp 16, lane 0) ----------------
        int slot = 0, ph = 1;
        for (int j = 0; j < KT; j++) {
            mbar_wait_relaxed(BAR_EMPTY(slot), (uint32_t)ph);
            MBARRIER_EXPECT_TX(BAR_FULL(slot), STG);
            const uint32_t sa = dynb + slot * STG;
            tma_load_2d(sa, &tmA, j * BK, m0, BAR_FULL(slot));
            tma_load_2d(sa + A_SZ, &tmB, j * BK, n0, BAR_FULL(slot));
            if (++slot == STAGES) { slot = 0; ph ^= 1; }
        }
    }

    __syncthreads();
    if (tid < BM) {
        const float v = fminf(fminf(srm[0][tid], srm[1][tid]),
                              fminf(srm[2][tid], srm[3][tid])) + g_esq[m0 + tid];
        atomicMin(&g_rowmin[m0 + tid], __float_as_uint(v));
    }

    // ---- last-CTA fused final reduction ----
    __threadfence();
    __syncthreads();
    if (tid == 0) s_last = atomicAdd(&g_done, 1u);
    __syncthreads();
    if (s_last == GRID_TILES - 1) {
        __threadfence();
        float s = 0.f;
        for (int i = tid; i < Mm; i += THREADS)
            s += __uint_as_float(g_rowmin[i]);
#pragma unroll
        for (int o = 16; o; o >>= 1) s += __shfl_xor_sync(0xffffffffu, s, o);
        if (lane == 0) ws[warp] = s;
        __syncthreads();
        if (tid == 0) {
            float tot = 0.f;
#pragma unroll
            for (int i = 0; i < 17; i++) tot += ws[i];
            out[0] = tot / (float)Mm;
        }
    }
}

// ================= host side =================
typedef CUresult (*EncodeTiledFn)(CUtensorMap*, CUtensorMapDataType, cuuint32_t, void*,
                                  const cuuint64_t*, const cuuint64_t*, const cuuint32_t*,
                                  const cuuint32_t*, CUtensorMapInterleave, CUtensorMapSwizzle,
                                  CUtensorMapL2promotion, CUtensorMapFloatOOBfill);

static void encode_map(EncodeTiledFn fn, CUtensorMap* tm, void* base) {
    cuuint64_t dims[2] = {(cuuint64_t)Dd, (cuuint64_t)Nn};
    cuuint64_t strides[1] = {(cuuint64_t)Dd * 2};
    cuuint32_t box[2] = {(cuuint32_t)BK, (cuuint32_t)BM};  // 64 bf16 x 128 rows
    cuuint32_t estr[2] = {1, 1};
    fn(tm, CU_TENSOR_MAP_DATA_TYPE_BFLOAT16, 2, base, dims, strides, box, estr,
       CU_TENSOR_MAP_INTERLEAVE_NONE, CU_TENSOR_MAP_SWIZZLE_128B,
       CU_TENSOR_MAP_L2_PROMOTION_L2_128B, CU_TENSOR_MAP_FLOAT_OOB_FILL_NONE);
}

extern "C" void kernel_launch(void* const* d_in, const int* in_sizes, int n_in,
                              void* d_out, int out_size) {
    const float* z = (const float*)d_in[0];  // [4096, 1024]
    const float* e = (const float*)d_in[1];  // [4096, 1024]
    float* out = (float*)d_out;              // [1]

    EncodeTiledFn enc = nullptr;
    {
        void* fn = nullptr;
#if CUDART_VERSION >= 12050
        cudaDriverEntryPointQueryResult qr;
        cudaGetDriverEntryPointByVersion("cuTensorMapEncodeTiled", &fn, 12000,
                                         cudaEnableDefault, &qr);
#else
        cudaGetDriverEntryPoint("cuTensorMapEncodeTiled", &fn, cudaEnableDefault);
#endif
        enc = (EncodeTiledFn)fn;
    }
    void *pe = nullptr, *pz = nullptr;
    cudaGetSymbolAddress(&pe, g_eb);
    cudaGetSymbolAddress(&pz, g_zb);
    CUtensorMap tmA, tmB;
    encode_map(enc, &tmA, pe);
    encode_map(enc, &tmB, pz);

    convert_kernel<<<(Nn + Mm) / 8, 256>>>(z, e);

    static bool attr_set = false;
    if (!attr_set) {
        cudaFuncSetAttribute(gemm_min_kernel, cudaFuncAttributeMaxDynamicSharedMemorySize,
                             DYN_SMEM);
        attr_set = true;
    }
    dim3 grid(Mm / BM, NSPLIT);  // 32 x 32 = 1024 CTAs
    gemm_min_kernel<<<grid, THREADS, DYN_SMEM>>>(out, tmA, tmB);
}

// round 11
// speedup vs baseline: 2.2176x; 1.1559x over previous
#include <cuda_runtime.h>
#include <cuda.h>
#include <cuda_fp16.h>
#include <cstdint>

// ---------------- problem constants ----------------
#define Nn 4096
#define Mm 4096
#define Dd 1024

// ---------------- GEMM tiling ----------------
#define BM 128
#define BN 128
#define BK 64                      // 64 fp16 = 128B rows (SW128 atom width)
#define KT (Dd / BK)               // 16 iterations
#define NSPLIT 32
#define STAGES 3
#define NCW 16                     // consumer warps (4m x 4n of 32x32 tiles)
#define THREADS (NCW * 32 + 32)    // +1 producer warp = 544

#define A_SZ (BM * 128)            // 16384 B
#define B_SZ (BN * 128)            // 16384 B
#define STG (A_SZ + B_SZ)          // 32768 B
#define DYN_SMEM (STAGES * STG + 1024)

// ---------------- scratch ----------------
__device__ __align__(256) __half g_zb[Nn * Dd];
__device__ __align__(256) __half g_eb[Mm * Dd];
__device__ __align__(256) float g_zsq[Nn];
__device__ __align__(256) unsigned g_rowmin[Mm];   // packed (valbits | 12-bit col)
__device__ unsigned long long g_acc;
__device__ unsigned g_cnt;

// ---------------- PTX helpers ----------------
#define MBARRIER_INIT(addr, cnt) \
    asm volatile("mbarrier.init.shared.b64 [%0], %1;" ::"r"(addr), "r"(cnt) : "memory")
#define MBARRIER_EXPECT_TX(addr, bytes) \
    asm volatile("mbarrier.arrive.expect_tx.shared.b64 _, [%0], %1;" ::"r"(addr), "r"(bytes) : "memory")
#define MBARRIER_ARRIVE(addr) \
    asm volatile("mbarrier.arrive.shared.b64 _, [%0];" ::"r"(addr) : "memory")

__device__ __forceinline__ void mbar_wait(uint32_t addr, uint32_t parity) {
    asm volatile(
        "{\n\t.reg .pred P;\n\t"
        "WL%=:\n\t"
        "mbarrier.try_wait.parity.acquire.cta.shared::cta.b64 P, [%0], %1, 0x989680;\n\t"
        "@P bra.uni WD%=;\n\t"
        "bra.uni WL%=;\n\t"
        "WD%=:\n\t}"
        ::"r"(addr), "r"(parity) : "memory");
}
__device__ __forceinline__ void mbar_wait_relaxed(uint32_t addr, uint32_t parity) {
    asm volatile(
        "{\n\t.reg .pred P;\n\t"
        "WL%=:\n\t"
        "mbarrier.try_wait.parity.relaxed.cta.shared::cta.b64 P, [%0], %1, 0x989680;\n\t"
        "@P bra.uni WD%=;\n\t"
        "bra.uni WL%=;\n\t"
        "WD%=:\n\t}"
        ::"r"(addr), "r"(parity) : "memory");
}

__device__ __forceinline__ void tma_load_2d(uint32_t smem_addr, const void* map,
                                            int cx, int cy, uint32_t mbar) {
    asm volatile(
        "cp.async.bulk.tensor.2d.shared::cta.global.tile.mbarrier::complete_tx::bytes "
        "[%0], [%1, {%2, %3}], [%4];"
        ::"r"(smem_addr), "l"(map), "r"(cx), "r"(cy), "r"(mbar)
        : "memory");
}

__device__ __forceinline__ void ldsm4(uint32_t* r, uint32_t saddr) {
    asm volatile("ldmatrix.sync.aligned.m8n8.x4.shared.b16 {%0,%1,%2,%3}, [%4];\n"
                 : "=r"(r[0]), "=r"(r[1]), "=r"(r[2]), "=r"(r[3])
                 : "r"(saddr));
}
// f16 accumulator mma: c = {2 x f16x2 regs}
__device__ __forceinline__ void mma16816_f16(uint32_t* c, const uint32_t* a,
                                             uint32_t b0, uint32_t b1) {
    asm volatile(
        "mma.sync.aligned.m16n8k16.row.col.f16.f16.f16.f16 "
        "{%0,%1}, {%2,%3,%4,%5}, {%6,%7}, {%0,%1};\n"
        : "+r"(c[0]), "+r"(c[1])
        : "r"(a[0]), "r"(a[1]), "r"(a[2]), "r"(a[3]), "r"(b0), "r"(b1));
}

// swizzled smem address of 16B chunk (row, cc) in a 128B-row SW128 tile
__device__ __forceinline__ uint32_t swz(uint32_t base, int row, int cc) {
    return base + ((uint32_t)row << 7) + (((uint32_t)(cc ^ (row & 7))) << 4);
}

// pack selection key: positive float bits (top 20) | 12-bit column
__device__ __forceinline__ unsigned packkey(float v, int col) {
    return (__float_as_uint(v) & 0xFFFFF000u) | (unsigned)col;
}

// ================= kernel 1: convert(fp16) + z norms + state init ==========
__global__ void __launch_bounds__(256) convert_kernel(const float* __restrict__ z,
                                                      const float* __restrict__ e) {
    if (blockIdx.x == 0) {
#pragma unroll
        for (int i = 0; i < Mm / 256; i++) g_rowmin[threadIdx.x + 256 * i] = 0xFFFFFFFFu;
        if (threadIdx.x == 0) { g_acc = 0ull; g_cnt = 0u; }
    }
    const int gwarp = (blockIdx.x * 256 + threadIdx.x) >> 5;
    const int lane = threadIdx.x & 31;
    const float* src;
    __half* dst;
    float* sqo = nullptr;
    if (gwarp < Nn) {
        src = z + (size_t)gwarp * Dd;
        dst = g_zb + (size_t)gwarp * Dd;
        sqo = g_zsq + gwarp;
    } else {
        const int r = gwarp - Nn;
        src = e + (size_t)r * Dd;
        dst = g_eb + (size_t)r * Dd;
    }
    float s = 0.f;
    const float4* s4 = reinterpret_cast<const float4*>(src);
    uint4* d4 = reinterpret_cast<uint4*>(dst);
#pragma unroll
    for (int i = 0; i < 4; i++) {
        const int idx = lane + 32 * i;
        float4 v0 = s4[2 * idx];
        float4 v1 = s4[2 * idx + 1];
        __half2 p0 = __floats2half2_rn(v0.x, v0.y);
        __half2 p1 = __floats2half2_rn(v0.z, v0.w);
        __half2 p2 = __floats2half2_rn(v1.x, v1.y);
        __half2 p3 = __floats2half2_rn(v1.z, v1.w);
        uint4 w;
        w.x = *reinterpret_cast<unsigned*>(&p0);
        w.y = *reinterpret_cast<unsigned*>(&p1);
        w.z = *reinterpret_cast<unsigned*>(&p2);
        w.w = *reinterpret_cast<unsigned*>(&p3);
        d4[idx] = w;
        s += v0.x * v0.x + v0.y * v0.y + v0.z * v0.z + v0.w * v0.w;
        s += v1.x * v1.x + v1.y * v1.y + v1.z * v1.z + v1.w * v1.w;
    }
    if (sqo) {
#pragma unroll
        for (int o = 16; o; o >>= 1) s += __shfl_xor_sync(0xffffffffu, s, o);
        if (lane == 0) *sqo = s;
    }
}

// ================= kernel 2: TMA-fed f16-acc GEMM + packed argmin =================
__global__ void __launch_bounds__(THREADS, 2) gemm_min_kernel(
    const __grid_constant__ CUtensorMap tmA,
    const __grid_constant__ CUtensorMap tmB) {
    extern __shared__ char dyn_raw[];
    __shared__ __align__(8) uint64_t s_bar[2 * STAGES];
    __shared__ unsigned srm[4][BM];

    uint32_t dynb = (uint32_t)__cvta_generic_to_shared(dyn_raw);
    dynb = (dynb + 1023u) & ~1023u;
    const uint32_t barb = (uint32_t)__cvta_generic_to_shared(s_bar);
#define BAR_FULL(s) (barb + (uint32_t)(s) * 8u)
#define BAR_EMPTY(s) (barb + (uint32_t)(STAGES + (s)) * 8u)

    const int tid = threadIdx.x;
    const int lane = tid & 31;
    const int warp = tid >> 5;

    const int m0 = blockIdx.x * BM;
    const int n0 = blockIdx.y * BN;

    if (tid == 0) {
#pragma unroll
        for (int s = 0; s < STAGES; s++) {
            MBARRIER_INIT(BAR_FULL(s), 1);
            MBARRIER_INIT(BAR_EMPTY(s), NCW);
        }
    }
    __syncthreads();

    if (warp < NCW) {
        // ---------------- consumers ----------------
        const int wm = warp >> 2;        // 0..3 : 32-row group
        const int wn = warp & 3;         // 0..3 : 32-col group
        const int ldrow = lane & 15;
        const int ldcc = lane >> 4;

        uint32_t acc[2][4][2];           // f16x2 accumulators (16 regs)
#pragma unroll
        for (int mi = 0; mi < 2; mi++)
#pragma unroll
            for (int g = 0; g < 4; g++) { acc[mi][g][0] = 0u; acc[mi][g][1] = 0u; }

        int slot = 0, ph = 0;
        for (int j = 0; j < KT; j++) {
            mbar_wait(BAR_FULL(slot), (uint32_t)ph);
            const uint32_t sa = dynb + slot * STG;
            const uint32_t sb = sa + A_SZ;

#pragma unroll
            for (int ks = 0; ks < 4; ks++) {
                const int cc = ks * 2 + ldcc;
                uint32_t a[2][4];
#pragma unroll
                for (int mi = 0; mi < 2; mi++)
                    ldsm4(a[mi], swz(sa, wm * 32 + mi * 16 + ldrow, cc));
                uint32_t b[2][4];
#pragma unroll
                for (int h = 0; h < 2; h++)
                    ldsm4(b[h], swz(sb, wn * 32 + h * 16 + ldrow, cc));
#pragma unroll
                for (int h = 0; h < 2; h++) {
#pragma unroll
                    for (int mi = 0; mi < 2; mi++) {
                        mma16816_f16(&acc[mi][2 * h][0], a[mi], b[h][0], b[h][2]);
                        mma16816_f16(&acc[mi][2 * h + 1][0], a[mi], b[h][1], b[h][3]);
                    }
                }
            }
            __syncwarp();
            if (lane == 0) MBARRIER_ARRIVE(BAR_EMPTY(slot));
            if (++slot == STAGES) { slot = 0; ph ^= 1; }
        }

        // ---- epilogue: packed argmin keys over this CTA's 128 columns ----
        unsigned rk0 = 0xFFFFFFFFu, rk1 = 0xFFFFFFFFu, rk2 = 0xFFFFFFFFu, rk3 = 0xFFFFFFFFu;
        const int colbase = n0 + wn * 32 + (lane & 3) * 2;
#pragma unroll
        for (int g = 0; g < 4; g++) {
            const int col = colbase + g * 8;
            const float zs0 = g_zsq[col] + 1024.f;   // shift keeps v positive
            const float zs1 = g_zsq[col + 1] + 1024.f;
#pragma unroll
            for (int mi = 0; mi < 2; mi++) {
                const __half2 h0 = *reinterpret_cast<const __half2*>(&acc[mi][g][0]);
                const __half2 h1 = *reinterpret_cast<const __half2*>(&acc[mi][g][1]);
                // rows: wm*32 + mi*16 + {q, q+8}
                const unsigned kA = min(packkey(fmaf(-2.f, __low2float(h0), zs0), col),
                                        packkey(fmaf(-2.f, __high2float(h0), zs1), col + 1));
                const unsigned kB = min(packkey(fmaf(-2.f, __low2float(h1), zs0), col),
                                        packkey(fmaf(-2.f, __high2float(h1), zs1), col + 1));
                if (mi == 0) { rk0 = min(rk0, kA); rk1 = min(rk1, kB); }
                else         { rk2 = min(rk2, kA); rk3 = min(rk3, kB); }
            }
        }
#pragma unroll
        for (int off = 1; off <= 2; off <<= 1) {
            rk0 = min(rk0, __shfl_xor_sync(0xffffffffu, rk0, off));
            rk1 = min(rk1, __shfl_xor_sync(0xffffffffu, rk1, off));
            rk2 = min(rk2, __shfl_xor_sync(0xffffffffu, rk2, off));
            rk3 = min(rk3, __shfl_xor_sync(0xffffffffu, rk3, off));
        }
        if ((lane & 3) == 0) {
            const int q = lane >> 2;
            srm[wn][wm * 32 + q] = rk0;
            srm[wn][wm * 32 + q + 8] = rk1;
            srm[wn][wm * 32 + 16 + q] = rk2;
            srm[wn][wm * 32 + 24 + q] = rk3;
        }
    } else if (lane == 0) {
        // ---------------- producer (warp 16, lane 0) ----------------
        int slot = 0, ph = 1;
        for (int j = 0; j < KT; j++) {
            mbar_wait_relaxed(BAR_EMPTY(slot), (uint32_t)ph);
            MBARRIER_EXPECT_TX(BAR_FULL(slot), STG);
            const uint32_t sa = dynb + slot * STG;
            tma_load_2d(sa, &tmA, j * BK, m0, BAR_FULL(slot));
            tma_load_2d(sa + A_SZ, &tmB, j * BK, n0, BAR_FULL(slot));
            if (++slot == STAGES) { slot = 0; ph ^= 1; }
        }
    }

    __syncthreads();
    if (tid < BM) {
        const unsigned k = min(min(srm[0][tid], srm[1][tid]), min(srm[2][tid], srm[3][tid]));
        atomicMin(&g_rowmin[m0 + tid], k);
    }
}

// ================= kernel 3: exact rerank + fused deterministic sum =================
__global__ void __launch_bounds__(256) rerank_kernel(const float* __restrict__ z,
                                                     const float* __restrict__ e,
                                                     float* __restrict__ out) {
    const int warp = threadIdx.x >> 5;
    const int lane = threadIdx.x & 31;
    const int m = blockIdx.x * 8 + warp;

    const int col = (int)(g_rowmin[m] & 0xFFFu);
    const float4* zp = reinterpret_cast<const float4*>(z + (size_t)col * Dd);
    const float4* ep = reinterpret_cast<const float4*>(e + (size_t)m * Dd);
    float d = 0.f;
#pragma unroll
    for (int i = 0; i < 8; i++) {
        const float4 a = zp[lane + 32 * i];
        const float4 b = ep[lane + 32 * i];
        const float dx = a.x - b.x, dy = a.y - b.y, dz = a.z - b.z, dw = a.w - b.w;
        d += dx * dx + dy * dy + dz * dz + dw * dw;
    }
#pragma unroll
    for (int o = 16; o; o >>= 1) d += __shfl_xor_sync(0xffffffffu, d, o);

    __shared__ float wsum[8];
    if (lane == 0) wsum[warp] = d;
    __syncthreads();
    if (threadIdx.x == 0) {
        float blk = 0.f;
#pragma unroll
        for (int i = 0; i < 8; i++) blk += wsum[i];
        // deterministic fixed-point accumulation (2^-24)
        atomicAdd(&g_acc, (unsigned long long)__double2ll_rn((double)blk * 16777216.0));
        __threadfence();
        const unsigned done = atomicAdd(&g_cnt, 1u);
        if (done == (Mm / 8) - 1) {
            const unsigned long long tot = atomicAdd(&g_acc, 0ull);
            out[0] = (float)((double)tot / 16777216.0 / (double)Mm);
        }
    }
}

// ================= host side =================
typedef CUresult (*EncodeTiledFn)(CUtensorMap*, CUtensorMapDataType, cuuint32_t, void*,
                                  const cuuint64_t*, const cuuint64_t*, const cuuint32_t*,
                                  const cuuint32_t*, CUtensorMapInterleave, CUtensorMapSwizzle,
                                  CUtensorMapL2promotion, CUtensorMapFloatOOBfill);

static void encode_map(EncodeTiledFn fn, CUtensorMap* tm, void* base) {
    cuuint64_t dims[2] = {(cuuint64_t)Dd, (cuuint64_t)Nn};
    cuuint64_t strides[1] = {(cuuint64_t)Dd * 2};
    cuuint32_t box[2] = {(cuuint32_t)BK, (cuuint32_t)BM};
    cuuint32_t estr[2] = {1, 1};
    fn(tm, CU_TENSOR_MAP_DATA_TYPE_FLOAT16, 2, base, dims, strides, box, estr,
       CU_TENSOR_MAP_INTERLEAVE_NONE, CU_TENSOR_MAP_SWIZZLE_128B,
       CU_TENSOR_MAP_L2_PROMOTION_L2_128B, CU_TENSOR_MAP_FLOAT_OOB_FILL_NONE);
}

extern "C" void kernel_launch(void* const* d_in, const int* in_sizes, int n_in,
                              void* d_out, int out_size) {
    const float* z = (const float*)d_in[0];  // [4096, 1024]
    const float* e = (const float*)d_in[1];  // [4096, 1024]
    float* out = (float*)d_out;              // [1]

    EncodeTiledFn enc = nullptr;
    {
        void* fn = nullptr;
#if CUDART_VERSION >= 12050
        cudaDriverEntryPointQueryResult qr;
        cudaGetDriverEntryPointByVersion("cuTensorMapEncodeTiled", &fn, 12000,
                                         cudaEnableDefault, &qr);
#else
        cudaGetDriverEntryPoint("cuTensorMapEncodeTiled", &fn, cudaEnableDefault);
#endif
        enc = (EncodeTiledFn)fn;
    }
    void *pe = nullptr, *pz = nullptr;
    cudaGetSymbolAddress(&pe, g_eb);
    cudaGetSymbolAddress(&pz, g_zb);
    CUtensorMap tmA, tmB;
    encode_map(enc, &tmA, pe);
    encode_map(enc, &tmB, pz);

    convert_kernel<<<(Nn + Mm) / 8, 256>>>(z, e);

    static bool attr_set = false;
    if (!attr_set) {
        cudaFuncSetAttribute(gemm_min_kernel, cudaFuncAttributeMaxDynamicSharedMemorySize,
                             DYN_SMEM);
        attr_set = true;
    }
    dim3 grid(Mm / BM, NSPLIT);  // 32 x 32 = 1024 CTAs
    gemm_min_kernel<<<grid, THREADS, DYN_SMEM>>>(tmA, tmB);

    rerank_kernel<<<Mm / 8, 256>>>(z, e, out);
}